// round 1
// baseline (speedup 1.0000x reference)
#include <cuda_runtime.h>
#include <cstdint>

// ---------------------------------------------------------------------------
// CausalAttention (random-feature attention), fp32 baseline.
//   T=2048 B=8 E=1024 H=16 D=64 K=64 (phi dim 2K=128), TAU=1, EPS=1e-6
//
// Pipeline:
//   1. prep:  Wq_eff = D^-0.5 * rm @ Wq(head-block),  Wk_eff = rm @ Wk
//   2. GEMM (mode PHI): phi_q = sincos(x @ Wq_eff^T + bq_eff) * K^-0.5
//   3. GEMM (mode PHI): phi_k = ...
//   4. GEMM (mode LIN): v = x @ Wv^T + bv
//   5. scan: causal linear attention recurrence, 128 (b,h) blocks
//   6. GEMM (mode LIN): out = attn @ Wo^T + bo
// ---------------------------------------------------------------------------

#define T_DIM 2048
#define B_DIM 8
#define E_DIM 1024
#define H_DIM 16
#define D_DIM 64
#define K_DIM 64
#define TB    (T_DIM * B_DIM)          // 16384 rows
#define PHI_W (2 * K_DIM)              // 128
#define EPS_RFA 1e-6f

// ------------------------- scratch (static device) -------------------------
__device__ float g_Wq_eff[E_DIM * E_DIM];
__device__ float g_Wk_eff[E_DIM * E_DIM];
__device__ float g_bq_eff[E_DIM];
__device__ float g_bk_eff[E_DIM];
__device__ float g_v   [TB * E_DIM];
__device__ float g_phiq[TB * H_DIM * PHI_W];
__device__ float g_phik[TB * H_DIM * PHI_W];
__device__ float g_attn[TB * E_DIM];

// ---------------------------------------------------------------------------
// Weight prep: Weff[h*64+k, e] = scale * sum_d rm[h,k,d] * W[h*64+d, e]
//              beff[h*64+k]    = scale * sum_d rm[h,k,d] * b[h*64+d]
// grid (16 e-tiles, 16 heads), 256 threads.
// ---------------------------------------------------------------------------
__global__ void __launch_bounds__(256) prep_weff(
    const float* __restrict__ rm, const float* __restrict__ W,
    const float* __restrict__ bvec, float* __restrict__ Weff,
    float* __restrict__ beff, float scale)
{
    const int h  = blockIdx.y;
    const int e0 = blockIdx.x * 64;
    const int tid = threadIdx.x;

    __shared__ float rs[64][65];   // rm[h][k][d]
    __shared__ float ws[64][65];   // W[h*64+d][e0+e]

    for (int i = tid; i < 4096; i += 256) {
        int k = i >> 6, dd = i & 63;
        rs[k][dd] = rm[h * 4096 + i];
    }
    for (int i = tid; i < 4096; i += 256) {
        int dd = i >> 6, e = i & 63;
        ws[dd][e] = W[(size_t)(h * 64 + dd) * E_DIM + e0 + e];
    }
    __syncthreads();

    const int tk = (tid >> 4) * 4;  // k base (0..60)
    const int te = (tid & 15) * 4;  // e base (0..60)
    float acc[4][4];
#pragma unroll
    for (int i = 0; i < 4; i++)
#pragma unroll
        for (int j = 0; j < 4; j++) acc[i][j] = 0.f;

#pragma unroll 8
    for (int dd = 0; dd < 64; dd++) {
        float a0 = rs[tk + 0][dd], a1 = rs[tk + 1][dd];
        float a2 = rs[tk + 2][dd], a3 = rs[tk + 3][dd];
        float b0 = ws[dd][te + 0], b1 = ws[dd][te + 1];
        float b2 = ws[dd][te + 2], b3 = ws[dd][te + 3];
        acc[0][0] += a0 * b0; acc[0][1] += a0 * b1; acc[0][2] += a0 * b2; acc[0][3] += a0 * b3;
        acc[1][0] += a1 * b0; acc[1][1] += a1 * b1; acc[1][2] += a1 * b2; acc[1][3] += a1 * b3;
        acc[2][0] += a2 * b0; acc[2][1] += a2 * b1; acc[2][2] += a2 * b2; acc[2][3] += a2 * b3;
        acc[3][0] += a3 * b0; acc[3][1] += a3 * b1; acc[3][2] += a3 * b2; acc[3][3] += a3 * b3;
    }
#pragma unroll
    for (int i = 0; i < 4; i++)
#pragma unroll
        for (int j = 0; j < 4; j++)
            Weff[(size_t)(h * 64 + tk + i) * E_DIM + e0 + te + j] = scale * acc[i][j];

    if (blockIdx.x == 0 && tid < 64) {
        float s = 0.f;
        for (int dd = 0; dd < 64; dd++) s += rs[tid][dd] * bvec[h * 64 + dd];
        beff[h * 64 + tid] = scale * s;
    }
}

// ---------------------------------------------------------------------------
// SGEMM NT:  C[m,n] = A[m,:] . B[n,:] + bias[n]    (A:[M,Kc] B:[N,Kc] row-major)
// MODE 0: plain write, row stride N.
// MODE 1: phi epilogue: p = acc+bias; h=col>>6; k=col&63;
//         C[row*2N + h*128 + k]      = sin(p)*K^-0.5
//         C[row*2N + h*128 + 64 + k] = cos(p)*K^-0.5
// 128x128x8 tiles, 256 threads, 8x8 microtile, double-buffered smem.
// Requires M%128==0, N%128==0, Kc%8==0.
// ---------------------------------------------------------------------------
template <int MODE>
__global__ void __launch_bounds__(256, 2) sgemm_nt(
    const float* __restrict__ A, const float* __restrict__ B,
    const float* __restrict__ bias, float* __restrict__ C,
    int M, int N, int Kc)
{
    const int m0 = blockIdx.y * 128;
    const int n0 = blockIdx.x * 128;
    const int tid = threadIdx.x;

    __shared__ float As[2][8][128];
    __shared__ float Bs[2][8][128];

    const int lrow = tid >> 1;
    const int lcol = (tid & 1) * 4;
    const float* Aptr = A + (size_t)(m0 + lrow) * Kc + lcol;
    const float* Bptr = B + (size_t)(n0 + lrow) * Kc + lcol;

    float4 a_ld = *(const float4*)Aptr;
    float4 b_ld = *(const float4*)Bptr;
    As[0][lcol + 0][lrow] = a_ld.x; As[0][lcol + 1][lrow] = a_ld.y;
    As[0][lcol + 2][lrow] = a_ld.z; As[0][lcol + 3][lrow] = a_ld.w;
    Bs[0][lcol + 0][lrow] = b_ld.x; Bs[0][lcol + 1][lrow] = b_ld.y;
    Bs[0][lcol + 2][lrow] = b_ld.z; Bs[0][lcol + 3][lrow] = b_ld.w;
    __syncthreads();

    const int tx = tid & 15;   // n direction
    const int ty = tid >> 4;   // m direction

    float acc[8][8];
#pragma unroll
    for (int i = 0; i < 8; i++)
#pragma unroll
        for (int j = 0; j < 8; j++) acc[i][j] = 0.f;

    const int nK = Kc >> 3;
#pragma unroll 1
    for (int kt = 0; kt < nK; kt++) {
        const int cur = kt & 1;
        if (kt + 1 < nK) {
            a_ld = *(const float4*)(Aptr + (size_t)(kt + 1) * 8);
            b_ld = *(const float4*)(Bptr + (size_t)(kt + 1) * 8);
        }
#pragma unroll
        for (int kk = 0; kk < 8; kk++) {
            float af[8], bf[8];
            *(float4*)&af[0] = *(const float4*)&As[cur][kk][ty * 4];
            *(float4*)&af[4] = *(const float4*)&As[cur][kk][64 + ty * 4];
            *(float4*)&bf[0] = *(const float4*)&Bs[cur][kk][tx * 4];
            *(float4*)&bf[4] = *(const float4*)&Bs[cur][kk][64 + tx * 4];
#pragma unroll
            for (int i = 0; i < 8; i++)
#pragma unroll
                for (int j = 0; j < 8; j++) acc[i][j] += af[i] * bf[j];
        }
        if (kt + 1 < nK) {
            const int nxt = cur ^ 1;
            As[nxt][lcol + 0][lrow] = a_ld.x; As[nxt][lcol + 1][lrow] = a_ld.y;
            As[nxt][lcol + 2][lrow] = a_ld.z; As[nxt][lcol + 3][lrow] = a_ld.w;
            Bs[nxt][lcol + 0][lrow] = b_ld.x; Bs[nxt][lcol + 1][lrow] = b_ld.y;
            Bs[nxt][lcol + 2][lrow] = b_ld.z; Bs[nxt][lcol + 3][lrow] = b_ld.w;
            __syncthreads();
        }
    }

    const float phi_scale = 0.125f;  // K^-0.5
#pragma unroll
    for (int im = 0; im < 2; im++) {
#pragma unroll
        for (int ii = 0; ii < 4; ii++) {
            const int row = m0 + im * 64 + ty * 4 + ii;
#pragma unroll
            for (int jn = 0; jn < 2; jn++) {
                const int colb = n0 + jn * 64 + tx * 4;
                if (MODE == 0) {
                    float4 r;
                    r.x = acc[im * 4 + ii][jn * 4 + 0] + bias[colb + 0];
                    r.y = acc[im * 4 + ii][jn * 4 + 1] + bias[colb + 1];
                    r.z = acc[im * 4 + ii][jn * 4 + 2] + bias[colb + 2];
                    r.w = acc[im * 4 + ii][jn * 4 + 3] + bias[colb + 3];
                    *(float4*)(C + (size_t)row * N + colb) = r;
                } else {
#pragma unroll
                    for (int j = 0; j < 4; j++) {
                        const int col = colb + j;
                        const float p = acc[im * 4 + ii][jn * 4 + j] + bias[col];
                        const int h = col >> 6, k = col & 63;
                        float sv, cv;
                        __sincosf(p, &sv, &cv);
                        float* base = C + (size_t)row * (2 * N) + h * 128 + k;
                        base[0]  = sv * phi_scale;
                        base[64] = cv * phi_scale;
                    }
                }
            }
        }
    }
}

// ---------------------------------------------------------------------------
// Causal RFA scan. One block per (b,h); 256 threads.
// thread tid: d = tid&63, kg = tid>>6 (0..3). Owns s[kg*32+j][d], j=0..31.
// ---------------------------------------------------------------------------
__global__ void __launch_bounds__(256) rfa_scan(
    const float* __restrict__ phiq, const float* __restrict__ phik,
    const float* __restrict__ v, float* __restrict__ attn)
{
    const int bx = blockIdx.x;       // b*16 + h
    const int h = bx & 15;
    const int b = bx >> 4;
    const int tid = threadIdx.x;
    const int d = tid & 63;
    const int kg = tid >> 6;

    __shared__ float s_pq[2][128], s_pk[2][128], s_v[2][64];
    __shared__ float s_z[128];
    __shared__ float s_red[256];
    __shared__ float s_qzp[4];

    float s_loc[32];
#pragma unroll
    for (int j = 0; j < 32; j++) s_loc[j] = 0.f;
    if (tid < 128) s_z[tid] = 0.f;

    const size_t phi_stride = (size_t)B_DIM * 2048;   // per-t stride in floats
    const size_t v_stride   = (size_t)B_DIM * 1024;
    const float* pq_base = phiq + (size_t)b * 2048 + h * 128;
    const float* pk_base = phik + (size_t)b * 2048 + h * 128;
    const float* v_base  = v    + (size_t)b * 1024 + h * 64;
    float*       o_base  = attn + (size_t)b * 1024 + h * 64;

    // preload t=0
    float ld_pq = 0.f, ld_pk = 0.f, ld_v = 0.f;
    if (tid < 128) { ld_pq = pq_base[tid]; ld_pk = pk_base[tid]; }
    if (tid < 64)  { ld_v = v_base[tid]; }
    int buf = 0;
    if (tid < 128) { s_pq[0][tid] = ld_pq; s_pk[0][tid] = ld_pk; }
    if (tid < 64)  { s_v[0][tid] = ld_v; }
    __syncthreads();

    for (int t = 0; t < T_DIM; t++) {
        // prefetch t+1 (gmem -> registers)
        if (t + 1 < T_DIM) {
            if (tid < 128) {
                ld_pq = pq_base[(size_t)(t + 1) * phi_stride + tid];
                ld_pk = pk_base[(size_t)(t + 1) * phi_stride + tid];
            }
            if (tid < 64) ld_v = v_base[(size_t)(t + 1) * v_stride + tid];
        }

        // main update: s += pk (x) v ; acc = sum_j pq_j * s_j  (this thread's kg slice)
        const float vd = s_v[buf][d];
        const float* pkp = &s_pk[buf][kg * 32];
        const float* pqp = &s_pq[buf][kg * 32];
        float acc0 = 0.f, acc1 = 0.f, acc2 = 0.f, acc3 = 0.f;
#pragma unroll
        for (int j = 0; j < 32; j += 4) {
            float4 pk4 = *(const float4*)(pkp + j);
            float4 pq4 = *(const float4*)(pqp + j);
            s_loc[j + 0] += pk4.x * vd; acc0 += pq4.x * s_loc[j + 0];
            s_loc[j + 1] += pk4.y * vd; acc1 += pq4.y * s_loc[j + 1];
            s_loc[j + 2] += pk4.z * vd; acc2 += pq4.z * s_loc[j + 2];
            s_loc[j + 3] += pk4.w * vd; acc3 += pq4.w * s_loc[j + 3];
        }
        s_red[tid] = (acc0 + acc1) + (acc2 + acc3);

        // z update + qz partials (threads 0..127, one per k)
        float qzp = 0.f;
        if (tid < 128) {
            float zn = s_z[tid] + s_pk[buf][tid];
            s_z[tid] = zn;
            qzp = s_pq[buf][tid] * zn;
        }
#pragma unroll
        for (int off = 16; off; off >>= 1)
            qzp += __shfl_xor_sync(0xffffffffu, qzp, off);
        if (tid < 128 && (tid & 31) == 0) s_qzp[tid >> 5] = qzp;
        __syncthreads();

        // finalize + write attn[t]
        if (tid < 64) {
            float qs = (s_red[d] + s_red[64 + d]) + (s_red[128 + d] + s_red[192 + d]);
            float qz = (s_qzp[0] + s_qzp[1]) + (s_qzp[2] + s_qzp[3]);
            qz = fmaxf(qz, EPS_RFA);
            o_base[(size_t)t * v_stride + d] = qs / qz;
        }

        // stage prefetched row into the other buffer
        buf ^= 1;
        if (t + 1 < T_DIM) {
            if (tid < 128) { s_pq[buf][tid] = ld_pq; s_pk[buf][tid] = ld_pk; }
            if (tid < 64)  { s_v[buf][tid] = ld_v; }
        }
        __syncthreads();
    }
}

// ---------------------------------------------------------------------------
extern "C" void kernel_launch(void* const* d_in, const int* in_sizes, int n_in,
                              void* d_out, int out_size)
{
    const float* x  = (const float*)d_in[0];
    const float* rm = (const float*)d_in[1];
    const float* Wq = (const float*)d_in[2];
    const float* bq = (const float*)d_in[3];
    const float* Wk = (const float*)d_in[4];
    const float* bk = (const float*)d_in[5];
    const float* Wv = (const float*)d_in[6];
    const float* bv = (const float*)d_in[7];
    const float* Wo = (const float*)d_in[8];
    const float* bo = (const float*)d_in[9];
    float* out = (float*)d_out;

    float *Wq_eff, *Wk_eff, *bq_eff, *bk_eff, *vbuf, *phiq, *phik, *attn;
    cudaGetSymbolAddress((void**)&Wq_eff, g_Wq_eff);
    cudaGetSymbolAddress((void**)&Wk_eff, g_Wk_eff);
    cudaGetSymbolAddress((void**)&bq_eff, g_bq_eff);
    cudaGetSymbolAddress((void**)&bk_eff, g_bk_eff);
    cudaGetSymbolAddress((void**)&vbuf,   g_v);
    cudaGetSymbolAddress((void**)&phiq,   g_phiq);
    cudaGetSymbolAddress((void**)&phik,   g_phik);
    cudaGetSymbolAddress((void**)&attn,   g_attn);

    // 1. fold rm (and q's D^-0.5 scale) into Q/K weights. TAU=1 so rm used as-is.
    prep_weff<<<dim3(16, 16), 256>>>(rm, Wq, bq, Wq_eff, bq_eff, 0.125f); // D^-0.5
    prep_weff<<<dim3(16, 16), 256>>>(rm, Wk, bk, Wk_eff, bk_eff, 1.0f);

    // 2-4. big GEMMs
    dim3 gg(E_DIM / 128, TB / 128);   // (8, 128)
    sgemm_nt<1><<<gg, 256>>>(x, Wq_eff, bq_eff, phiq, TB, E_DIM, E_DIM);
    sgemm_nt<1><<<gg, 256>>>(x, Wk_eff, bk_eff, phik, TB, E_DIM, E_DIM);
    sgemm_nt<0><<<gg, 256>>>(x, Wv, bv, vbuf, TB, E_DIM, E_DIM);

    // 5. causal scan
    rfa_scan<<<B_DIM * H_DIM, 256>>>(phiq, phik, vbuf, attn);

    // 6. output projection
    sgemm_nt<0><<<gg, 256>>>(attn, Wo, bo, out, TB, E_DIM, E_DIM);
}

// round 6
// speedup vs baseline: 1.4968x; 1.4968x over previous
#include <cuda_runtime.h>
#include <cuda_fp16.h>
#include <cuda_bf16.h>
#include <cstdint>
#include <type_traits>

// ---------------------------------------------------------------------------
// CausalAttention (random-feature attention) — mma.sync 3-term split GEMMs
// with per-chunk RN accumulator drain (HMMA accumulate chains limited to 6).
//   phi_q/phi_k/v GEMMs: fp16 split, x pre-scaled x256, weights x64.
//   output GEMM: bf16 split (attn can spike ~1e6; bf16 has fp32 range).
// ---------------------------------------------------------------------------

#define T_DIM 2048
#define B_DIM 8
#define E_DIM 1024
#define H_DIM 16
#define TB    (T_DIM * B_DIM)          // 16384 rows
#define EPS_RFA 1e-6f

#define BM 128
#define BN 128
#define BK 32
#define NKT (E_DIM / BK)                // 32
#define ROW_B 80
#define ARR_B (128 * ROW_B)
#define STAGE_B (4 * ARR_B)
#define NSTAGE 3
#define SM_BIAS 0
#define SM_STAGE0 1024
#define SM_TOTAL (SM_STAGE0 + NSTAGE * STAGE_B)   // 123904

// ------------------------- scratch (static device) -------------------------
__device__ __half g_x_hi[TB * E_DIM];
__device__ __half g_x_lo[TB * E_DIM];
__device__ __half g_Wq_hi[E_DIM * E_DIM];
__device__ __half g_Wq_lo[E_DIM * E_DIM];
__device__ __half g_Wk_hi[E_DIM * E_DIM];
__device__ __half g_Wk_lo[E_DIM * E_DIM];
__device__ __half g_Wv_hi[E_DIM * E_DIM];
__device__ __half g_Wv_lo[E_DIM * E_DIM];
__device__ __nv_bfloat16 g_Wo_hi[E_DIM * E_DIM];
__device__ __nv_bfloat16 g_Wo_lo[E_DIM * E_DIM];
__device__ float g_bq_eff[E_DIM];
__device__ float g_bk_eff[E_DIM];
__device__ float g_v   [TB * E_DIM];
__device__ float g_phiq[(size_t)TB * 2048];
__device__ float g_phik[(size_t)TB * 2048];
__device__ __nv_bfloat16 g_attn_hi[TB * E_DIM];
__device__ __nv_bfloat16 g_attn_lo[TB * E_DIM];

// ----------------------------- PTX helpers ---------------------------------
__device__ __forceinline__ uint32_t smem_to_u32(const void* p) {
    uint32_t a;
    asm("{ .reg .u64 t; cvta.to.shared.u64 t, %1; cvt.u32.u64 %0, t; }" : "=r"(a) : "l"(p));
    return a;
}
__device__ __forceinline__ void cp16(uint32_t dst, const void* src) {
    asm volatile("cp.async.cg.shared.global [%0], [%1], 16;" :: "r"(dst), "l"(src) : "memory");
}
#define CP_COMMIT() asm volatile("cp.async.commit_group;" ::: "memory")
#define CP_WAIT2()  asm volatile("cp.async.wait_group 2;" ::: "memory")

__device__ __forceinline__ void ldsm4(uint32_t* r, uint32_t addr) {
    asm volatile("ldmatrix.sync.aligned.m8n8.x4.shared.b16 {%0,%1,%2,%3}, [%4];"
                 : "=r"(r[0]), "=r"(r[1]), "=r"(r[2]), "=r"(r[3]) : "r"(addr));
}
__device__ __forceinline__ void mma_f16(float* d, const uint32_t* a, const uint32_t* b) {
    asm volatile(
        "mma.sync.aligned.m16n8k16.row.col.f32.f16.f16.f32 "
        "{%0,%1,%2,%3}, {%4,%5,%6,%7}, {%8,%9}, {%0,%1,%2,%3};"
        : "+f"(d[0]), "+f"(d[1]), "+f"(d[2]), "+f"(d[3])
        : "r"(a[0]), "r"(a[1]), "r"(a[2]), "r"(a[3]), "r"(b[0]), "r"(b[1]));
}
__device__ __forceinline__ void mma_bf16(float* d, const uint32_t* a, const uint32_t* b) {
    asm volatile(
        "mma.sync.aligned.m16n8k16.row.col.f32.bf16.bf16.f32 "
        "{%0,%1,%2,%3}, {%4,%5,%6,%7}, {%8,%9}, {%0,%1,%2,%3};"
        : "+f"(d[0]), "+f"(d[1]), "+f"(d[2]), "+f"(d[3])
        : "r"(a[0]), "r"(a[1]), "r"(a[2]), "r"(a[3]), "r"(b[0]), "r"(b[1]));
}

// ---------------------------------------------------------------------------
// fp32 -> fp16 hi/lo split (with pre-scale)
// ---------------------------------------------------------------------------
__global__ void __launch_bounds__(256) f32_to_f16hl(
    const float* __restrict__ in, __half* __restrict__ hi,
    __half* __restrict__ lo, int n, float scale)
{
    int i = (blockIdx.x * 256 + threadIdx.x) * 4;
    if (i >= n) return;
    float4 v = *(const float4*)(in + i);
    float a[4] = {v.x * scale, v.y * scale, v.z * scale, v.w * scale};
    __half h[4], l[4];
#pragma unroll
    for (int j = 0; j < 4; j++) {
        h[j] = __float2half_rn(a[j]);
        l[j] = __float2half_rn(a[j] - __half2float(h[j]));
    }
    *(__half2*)(hi + i)     = __halves2half2(h[0], h[1]);
    *(__half2*)(hi + i + 2) = __halves2half2(h[2], h[3]);
    *(__half2*)(lo + i)     = __halves2half2(l[0], l[1]);
    *(__half2*)(lo + i + 2) = __halves2half2(l[2], l[3]);
}

// fp32 -> bf16 hi/lo split
__global__ void __launch_bounds__(256) f32_to_bf16hl(
    const float* __restrict__ in, __nv_bfloat16* __restrict__ hi,
    __nv_bfloat16* __restrict__ lo, int n)
{
    int i = (blockIdx.x * 256 + threadIdx.x) * 4;
    if (i >= n) return;
    float4 v = *(const float4*)(in + i);
    float a[4] = {v.x, v.y, v.z, v.w};
    __nv_bfloat16 h[4], l[4];
#pragma unroll
    for (int j = 0; j < 4; j++) {
        h[j] = __float2bfloat16(a[j]);
        l[j] = __float2bfloat16(a[j] - __bfloat162float(h[j]));
    }
    *(__nv_bfloat162*)(hi + i)     = __halves2bfloat162(h[0], h[1]);
    *(__nv_bfloat162*)(hi + i + 2) = __halves2bfloat162(h[2], h[3]);
    *(__nv_bfloat162*)(lo + i)     = __halves2bfloat162(l[0], l[1]);
    *(__nv_bfloat162*)(lo + i + 2) = __halves2bfloat162(l[2], l[3]);
}

// ---------------------------------------------------------------------------
// Weight prep: Weff[h*64+k, e] = scale * sum_d rm[h,k,d] * W[h*64+d, e]
// matrix written as fp16 hi/lo with extra x64; beff fp32 (logical scale).
// ---------------------------------------------------------------------------
__global__ void __launch_bounds__(256) prep_weff(
    const float* __restrict__ rm, const float* __restrict__ W,
    const float* __restrict__ bvec, __half* __restrict__ Whi,
    __half* __restrict__ Wlo, float* __restrict__ beff, float scale)
{
    const int h  = blockIdx.y;
    const int e0 = blockIdx.x * 64;
    const int tid = threadIdx.x;

    __shared__ float rs[64][65];
    __shared__ float ws[64][65];

    for (int i = tid; i < 4096; i += 256) {
        int k = i >> 6, dd = i & 63;
        rs[k][dd] = rm[h * 4096 + i];
    }
    for (int i = tid; i < 4096; i += 256) {
        int dd = i >> 6, e = i & 63;
        ws[dd][e] = W[(size_t)(h * 64 + dd) * E_DIM + e0 + e];
    }
    __syncthreads();

    const int tk = (tid >> 4) * 4;
    const int te = (tid & 15) * 4;
    float acc[4][4];
#pragma unroll
    for (int i = 0; i < 4; i++)
#pragma unroll
        for (int j = 0; j < 4; j++) acc[i][j] = 0.f;

#pragma unroll 8
    for (int dd = 0; dd < 64; dd++) {
        float a0 = rs[tk + 0][dd], a1 = rs[tk + 1][dd];
        float a2 = rs[tk + 2][dd], a3 = rs[tk + 3][dd];
        float b0 = ws[dd][te + 0], b1 = ws[dd][te + 1];
        float b2 = ws[dd][te + 2], b3 = ws[dd][te + 3];
        acc[0][0] += a0 * b0; acc[0][1] += a0 * b1; acc[0][2] += a0 * b2; acc[0][3] += a0 * b3;
        acc[1][0] += a1 * b0; acc[1][1] += a1 * b1; acc[1][2] += a1 * b2; acc[1][3] += a1 * b3;
        acc[2][0] += a2 * b0; acc[2][1] += a2 * b1; acc[2][2] += a2 * b2; acc[2][3] += a2 * b3;
        acc[3][0] += a3 * b0; acc[3][1] += a3 * b1; acc[3][2] += a3 * b2; acc[3][3] += a3 * b3;
    }
#pragma unroll
    for (int i = 0; i < 4; i++)
#pragma unroll
        for (int j = 0; j < 4; j++) {
            float val = 64.f * scale * acc[i][j];     // x64 for fp16 lo range
            size_t idx = (size_t)(h * 64 + tk + i) * E_DIM + e0 + te + j;
            __half hv = __float2half_rn(val);
            Whi[idx] = hv;
            Wlo[idx] = __float2half_rn(val - __half2float(hv));
        }

    if (blockIdx.x == 0 && tid < 64) {
        float s = 0.f;
        for (int dd = 0; dd < 64; dd++) s += rs[tid][dd] * bvec[h * 64 + dd];
        beff[h * 64 + tid] = scale * s;               // bias stays logical
    }
}

// ---------------------------------------------------------------------------
// one k-stage loader
// ---------------------------------------------------------------------------
template <typename ET>
__device__ __forceinline__ void load_stage(
    const ET* __restrict__ Ahi, const ET* __restrict__ Alo,
    const ET* __restrict__ Bhi, const ET* __restrict__ Blo,
    int m0, int n0, int kc0, uint32_t st, int tid)
{
#pragma unroll
    for (int i = 0; i < 2; i++) {
        const int idx = tid + 256 * i;
        const int row = idx >> 2;
        const int u = idx & 3;
        const uint32_t doff = row * ROW_B + u * 16;
        const size_t aoff = (size_t)(m0 + row) * E_DIM + kc0 + u * 8;
        const size_t boff = (size_t)(n0 + row) * E_DIM + kc0 + u * 8;
        cp16(st + doff,             Ahi + aoff);
        cp16(st + ARR_B + doff,     Alo + aoff);
        cp16(st + 2 * ARR_B + doff, Bhi + boff);
        cp16(st + 3 * ARR_B + doff, Blo + boff);
    }
}

// ---------------------------------------------------------------------------
// HMMA GEMM: C = escale * (A @ B^T) + bias, 3-term split, per-chunk RN drain.
// MODE 0: C fp32, row stride 1024.   MODE 1: phi epilogue, row stride 2048.
// ---------------------------------------------------------------------------
template <int MODE, typename ET>
__global__ void __launch_bounds__(256, 1) tc_gemm(
    const ET* __restrict__ Ahi, const ET* __restrict__ Alo,
    const ET* __restrict__ Bhi, const ET* __restrict__ Blo,
    const float* __restrict__ bias, float* __restrict__ Cout, float escale)
{
    extern __shared__ char smem[];
    const uint32_t sbase = smem_to_u32(smem);
    const int tid = threadIdx.x;
    const int wid = tid >> 5;
    const int lane = tid & 31;
    const int m0 = blockIdx.y * BM;
    const int n0 = blockIdx.x * BN;

    float* bias_s = (float*)(smem + SM_BIAS);
    if (tid < 128) bias_s[tid] = bias[n0 + tid];

    const int wm = wid >> 1;
    const int wn = wid & 1;
    const int g = lane >> 3;
    const int r = lane & 7;

#pragma unroll
    for (int s = 0; s < NSTAGE; s++) {
        load_stage(Ahi, Alo, Bhi, Blo, m0, n0, s * BK,
                   sbase + SM_STAGE0 + s * STAGE_B, tid);
        CP_COMMIT();
    }

    float accm[2][8][4];   // master (IEEE-RN accumulated)
    float accw[2][8][4];   // working (HMMA chunk accumulator)
#pragma unroll
    for (int mt = 0; mt < 2; mt++)
#pragma unroll
        for (int j = 0; j < 8; j++)
#pragma unroll
            for (int c = 0; c < 4; c++) { accm[mt][j][c] = 0.f; accw[mt][j][c] = 0.f; }

    const uint32_t a_row_off = (uint32_t)((wm * 32 + (g & 1) * 8 + r) * ROW_B + (g >> 1) * 16);
    const uint32_t b_row_off = (uint32_t)((wn * 64 + (g >> 1) * 8 + r) * ROW_B + (g & 1) * 16);

#pragma unroll 1
    for (int kt = 0; kt < NKT; kt++) {
        CP_WAIT2();
        __syncthreads();
        const uint32_t st = sbase + SM_STAGE0 + (kt % NSTAGE) * STAGE_B;
        const uint32_t sA[2] = { st, st + ARR_B };
        const uint32_t sB[2] = { st + 2 * ARR_B, st + 3 * ARR_B };

#pragma unroll
        for (int ks = 0; ks < 2; ks++) {
            uint32_t afr[2][2][4];
            uint32_t bfr[4][2][4];
#pragma unroll
            for (int mt = 0; mt < 2; mt++)
#pragma unroll
                for (int hl = 0; hl < 2; hl++)
                    ldsm4(afr[mt][hl], sA[hl] + a_row_off + mt * (16 * ROW_B) + ks * 32);
#pragma unroll
            for (int jp = 0; jp < 4; jp++)
#pragma unroll
                for (int hl = 0; hl < 2; hl++)
                    ldsm4(bfr[jp][hl], sB[hl] + b_row_off + jp * (16 * ROW_B) + ks * 32);

#pragma unroll
            for (int t = 0; t < 3; t++) {
                const int pa = (t == 2) ? 1 : 0;   // hh, hl, lh
                const int pb = (t == 1) ? 1 : 0;
#pragma unroll
                for (int mt = 0; mt < 2; mt++)
#pragma unroll
                    for (int j = 0; j < 8; j++) {
                        if (std::is_same<ET, __half>::value)
                            mma_f16(accw[mt][j], afr[mt][pa], &bfr[j >> 1][pb][(j & 1) * 2]);
                        else
                            mma_bf16(accw[mt][j], afr[mt][pa], &bfr[j >> 1][pb][(j & 1) * 2]);
                    }
            }
        }
        // drain working -> master with IEEE-RN adds; re-zero working.
#pragma unroll
        for (int mt = 0; mt < 2; mt++)
#pragma unroll
            for (int j = 0; j < 8; j++)
#pragma unroll
                for (int c = 0; c < 4; c++) {
                    accm[mt][j][c] += accw[mt][j][c];
                    accw[mt][j][c] = 0.f;
                }

        __syncthreads();
        if (kt + NSTAGE < NKT)
            load_stage(Ahi, Alo, Bhi, Blo, m0, n0, (kt + NSTAGE) * BK,
                       sbase + SM_STAGE0 + (kt % NSTAGE) * STAGE_B, tid);
        CP_COMMIT();
    }

    // ------------------------------ epilogue --------------------------------
    const int qr = lane >> 2;
    const int qc = (lane & 3) * 2;
#pragma unroll
    for (int mt = 0; mt < 2; mt++) {
        const int row0 = m0 + wm * 32 + mt * 16 + qr;
#pragma unroll
        for (int j = 0; j < 8; j++) {
            const int coll = wn * 64 + j * 8 + qc;
            const int col = n0 + coll;
            const float b0 = bias_s[coll], b1 = bias_s[coll + 1];
            if (MODE == 0) {
                float2 v0 = make_float2(accm[mt][j][0] * escale + b0,
                                        accm[mt][j][1] * escale + b1);
                float2 v1 = make_float2(accm[mt][j][2] * escale + b0,
                                        accm[mt][j][3] * escale + b1);
                *(float2*)(Cout + (size_t)row0 * E_DIM + col) = v0;
                *(float2*)(Cout + (size_t)(row0 + 8) * E_DIM + col) = v1;
            } else {
                const int h = col >> 6, k = col & 63;
                float s0, c0s, s1, c1s, s2, c2s, s3, c3s;
                __sincosf(accm[mt][j][0] * escale + b0, &s0, &c0s);
                __sincosf(accm[mt][j][1] * escale + b1, &s1, &c1s);
                __sincosf(accm[mt][j][2] * escale + b0, &s2, &c2s);
                __sincosf(accm[mt][j][3] * escale + b1, &s3, &c3s);
                float* p0 = Cout + (size_t)row0 * 2048 + h * 128 + k;
                float* p1 = Cout + (size_t)(row0 + 8) * 2048 + h * 128 + k;
                p0[0] = s0 * 0.125f; p0[1]  = s1 * 0.125f;
                p0[64] = c0s * 0.125f; p0[65] = c1s * 0.125f;
                p1[0] = s2 * 0.125f; p1[1]  = s3 * 0.125f;
                p1[64] = c2s * 0.125f; p1[65] = c3s * 0.125f;
            }
        }
    }
}

// ---------------------------------------------------------------------------
// Causal RFA scan. One block per (b,h); 256 threads. attn -> bf16 hi/lo.
// ---------------------------------------------------------------------------
__global__ void __launch_bounds__(256) rfa_scan(
    const float* __restrict__ phiq, const float* __restrict__ phik,
    const float* __restrict__ v, __nv_bfloat16* __restrict__ attn_hi,
    __nv_bfloat16* __restrict__ attn_lo)
{
    const int bx = blockIdx.x;
    const int h = bx & 15;
    const int b = bx >> 4;
    const int tid = threadIdx.x;
    const int d = tid & 63;
    const int kg = tid >> 6;

    __shared__ float s_pq[2][128], s_pk[2][128], s_v[2][64];
    __shared__ float s_z[128];
    __shared__ float s_red[256];
    __shared__ float s_qzp[4];

    float s_loc[32];
#pragma unroll
    for (int j = 0; j < 32; j++) s_loc[j] = 0.f;
    if (tid < 128) s_z[tid] = 0.f;

    const size_t phi_stride = (size_t)B_DIM * 2048;
    const size_t v_stride   = (size_t)B_DIM * 1024;
    const float* pq_base = phiq + (size_t)b * 2048 + h * 128;
    const float* pk_base = phik + (size_t)b * 2048 + h * 128;
    const float* v_base  = v    + (size_t)b * 1024 + h * 64;
    const size_t o_off   = (size_t)b * 1024 + h * 64;

    float ld_pq = 0.f, ld_pk = 0.f, ld_v = 0.f;
    if (tid < 128) { ld_pq = pq_base[tid]; ld_pk = pk_base[tid]; }
    if (tid < 64)  { ld_v = v_base[tid]; }
    int buf = 0;
    if (tid < 128) { s_pq[0][tid] = ld_pq; s_pk[0][tid] = ld_pk; }
    if (tid < 64)  { s_v[0][tid] = ld_v; }
    __syncthreads();

    for (int t = 0; t < T_DIM; t++) {
        if (t + 1 < T_DIM) {
            if (tid < 128) {
                ld_pq = pq_base[(size_t)(t + 1) * phi_stride + tid];
                ld_pk = pk_base[(size_t)(t + 1) * phi_stride + tid];
            }
            if (tid < 64) ld_v = v_base[(size_t)(t + 1) * v_stride + tid];
        }

        const float vd = s_v[buf][d];
        const float* pkp = &s_pk[buf][kg * 32];
        const float* pqp = &s_pq[buf][kg * 32];
        float acc0 = 0.f, acc1 = 0.f, acc2 = 0.f, acc3 = 0.f;
#pragma unroll
        for (int j = 0; j < 32; j += 4) {
            float4 pk4 = *(const float4*)(pkp + j);
            float4 pq4 = *(const float4*)(pqp + j);
            s_loc[j + 0] += pk4.x * vd; acc0 += pq4.x * s_loc[j + 0];
            s_loc[j + 1] += pk4.y * vd; acc1 += pq4.y * s_loc[j + 1];
            s_loc[j + 2] += pk4.z * vd; acc2 += pq4.z * s_loc[j + 2];
            s_loc[j + 3] += pk4.w * vd; acc3 += pq4.w * s_loc[j + 3];
        }
        s_red[tid] = (acc0 + acc1) + (acc2 + acc3);

        float qzp = 0.f;
        if (tid < 128) {
            float zn = s_z[tid] + s_pk[buf][tid];
            s_z[tid] = zn;
            qzp = s_pq[buf][tid] * zn;
        }
#pragma unroll
        for (int off = 16; off; off >>= 1)
            qzp += __shfl_xor_sync(0xffffffffu, qzp, off);
        if (tid < 128 && (tid & 31) == 0) s_qzp[tid >> 5] = qzp;
        __syncthreads();

        if (tid < 64) {
            float qs = (s_red[d] + s_red[64 + d]) + (s_red[128 + d] + s_red[192 + d]);
            float qz = (s_qzp[0] + s_qzp[1]) + (s_qzp[2] + s_qzp[3]);
            qz = fmaxf(qz, EPS_RFA);
            float o = qs / qz;
            __nv_bfloat16 hv = __float2bfloat16(o);
            size_t idx = (size_t)t * v_stride + o_off + d;
            attn_hi[idx] = hv;
            attn_lo[idx] = __float2bfloat16(o - __bfloat162float(hv));
        }

        buf ^= 1;
        if (t + 1 < T_DIM) {
            if (tid < 128) { s_pq[buf][tid] = ld_pq; s_pk[buf][tid] = ld_pk; }
            if (tid < 64)  { s_v[buf][tid] = ld_v; }
        }
        __syncthreads();
    }
}

// ---------------------------------------------------------------------------
extern "C" void kernel_launch(void* const* d_in, const int* in_sizes, int n_in,
                              void* d_out, int out_size)
{
    const float* x  = (const float*)d_in[0];
    const float* rm = (const float*)d_in[1];
    const float* Wq = (const float*)d_in[2];
    const float* bq = (const float*)d_in[3];
    const float* Wk = (const float*)d_in[4];
    const float* bk = (const float*)d_in[5];
    const float* Wv = (const float*)d_in[6];
    const float* bv = (const float*)d_in[7];
    const float* Wo = (const float*)d_in[8];
    const float* bo = (const float*)d_in[9];
    float* out = (float*)d_out;

    __half *x_hi, *x_lo, *Wq_hi, *Wq_lo, *Wk_hi, *Wk_lo, *Wv_hi, *Wv_lo;
    __nv_bfloat16 *Wo_hi, *Wo_lo, *attn_hi, *attn_lo;
    float *bq_eff, *bk_eff, *vbuf, *phiq, *phik;
    cudaGetSymbolAddress((void**)&x_hi, g_x_hi);
    cudaGetSymbolAddress((void**)&x_lo, g_x_lo);
    cudaGetSymbolAddress((void**)&Wq_hi, g_Wq_hi);
    cudaGetSymbolAddress((void**)&Wq_lo, g_Wq_lo);
    cudaGetSymbolAddress((void**)&Wk_hi, g_Wk_hi);
    cudaGetSymbolAddress((void**)&Wk_lo, g_Wk_lo);
    cudaGetSymbolAddress((void**)&Wv_hi, g_Wv_hi);
    cudaGetSymbolAddress((void**)&Wv_lo, g_Wv_lo);
    cudaGetSymbolAddress((void**)&Wo_hi, g_Wo_hi);
    cudaGetSymbolAddress((void**)&Wo_lo, g_Wo_lo);
    cudaGetSymbolAddress((void**)&attn_hi, g_attn_hi);
    cudaGetSymbolAddress((void**)&attn_lo, g_attn_lo);
    cudaGetSymbolAddress((void**)&bq_eff, g_bq_eff);
    cudaGetSymbolAddress((void**)&bk_eff, g_bk_eff);
    cudaGetSymbolAddress((void**)&vbuf, g_v);
    cudaGetSymbolAddress((void**)&phiq, g_phiq);
    cudaGetSymbolAddress((void**)&phik, g_phik);

    cudaFuncSetAttribute((const void*)tc_gemm<0, __half>,
                         cudaFuncAttributeMaxDynamicSharedMemorySize, SM_TOTAL);
    cudaFuncSetAttribute((const void*)tc_gemm<1, __half>,
                         cudaFuncAttributeMaxDynamicSharedMemorySize, SM_TOTAL);
    cudaFuncSetAttribute((const void*)tc_gemm<0, __nv_bfloat16>,
                         cudaFuncAttributeMaxDynamicSharedMemorySize, SM_TOTAL);

    // conversions + weight prep: x scaled x256 (keeps fp16 lo normal),
    // fp16 weights x64; bf16 Wo unscaled.
    f32_to_f16hl<<<TB * E_DIM / 1024, 256>>>(x, x_hi, x_lo, TB * E_DIM, 256.0f);
    prep_weff<<<dim3(16, 16), 256>>>(rm, Wq, bq, Wq_hi, Wq_lo, bq_eff, 0.125f);
    prep_weff<<<dim3(16, 16), 256>>>(rm, Wk, bk, Wk_hi, Wk_lo, bk_eff, 1.0f);
    f32_to_f16hl<<<E_DIM * E_DIM / 1024, 256>>>(Wv, Wv_hi, Wv_lo, E_DIM * E_DIM, 64.0f);
    f32_to_bf16hl<<<E_DIM * E_DIM / 1024, 256>>>(Wo, Wo_hi, Wo_lo, E_DIM * E_DIM);

    // tensor-core GEMMs (escale undoes x256 * x64)
    dim3 gg(E_DIM / BN, TB / BM);   // (8, 128)
    const float inv = 1.0f / 16384.0f;
    tc_gemm<1, __half><<<gg, 256, SM_TOTAL>>>(x_hi, x_lo, Wq_hi, Wq_lo, bq_eff, phiq, inv);
    tc_gemm<1, __half><<<gg, 256, SM_TOTAL>>>(x_hi, x_lo, Wk_hi, Wk_lo, bk_eff, phik, inv);
    tc_gemm<0, __half><<<gg, 256, SM_TOTAL>>>(x_hi, x_lo, Wv_hi, Wv_lo, bv, vbuf, inv);

    // causal scan (writes attn bf16 split)
    rfa_scan<<<B_DIM * H_DIM, 256>>>(phiq, phik, vbuf, attn_hi, attn_lo);

    // output projection (bf16 split, unamplified error path)
    tc_gemm<0, __nv_bfloat16><<<gg, 256, SM_TOTAL>>>(attn_hi, attn_lo, Wo_hi, Wo_lo, bo, out, 1.0f);
}